// round 3
// baseline (speedup 1.0000x reference)
#include <cuda_runtime.h>
#include <cstdint>

#define SEQ 2048
#define BATCH 2
#define DMODEL 1024
#define NHEADS 16
#define DHEAD 64
#define BHD (BATCH*NHEADS)

// Single consolidated scratch buffer (allocation-free rule: __device__ global).
// Layout: [q | k | v | inter], each BHD*SEQ*DHEAD = 4M floats (16 MB).
#define QKV_ELEMS (BHD*SEQ*DHEAD)       // 4,194,304
__device__ float g_scratch[4 * QKV_ELEMS];
#define G_Q     (g_scratch)
#define G_K     (g_scratch + QKV_ELEMS)
#define G_V     (g_scratch + 2*QKV_ELEMS)
#define G_INTER (g_scratch + 3*QKV_ELEMS)   // viewed as [B,S,D]

// ---------------------------------------------------------------------------
// SGEMM NT: C[M,N] = A[M,K] * Bm[N,K]^T + bias[N]
// MODE 0: plain write to C, A from param.
// MODE 1: A from param, scatter into q/k/v ([B,H,S,Dh]).
// MODE 2: A = G_INTER (device global), plain write to C.
// BM=BN=128, BK=16, 256 threads, 8x8 per-thread tile.
// ---------------------------------------------------------------------------
template<int MODE>
__global__ __launch_bounds__(256)
void sgemm_nt(const float* __restrict__ Ap, const float* __restrict__ Bm,
              const float* __restrict__ bias, float* __restrict__ C,
              int M, int N, int Kd)
{
    constexpr int BM = 128, BN = 128, BK = 16;
    __shared__ float As[BK][BM + 4];
    __shared__ float Bs[BK][BN + 4];

    const float* A = (MODE == 2) ? G_INTER : Ap;

    const int tid = threadIdx.x;
    const int tx = tid & 15;      // 0..15 -> n
    const int ty = tid >> 4;      // 0..15 -> m
    const int m0 = blockIdx.y * BM;
    const int n0 = blockIdx.x * BN;

    float acc[8][8];
#pragma unroll
    for (int i = 0; i < 8; i++)
#pragma unroll
        for (int j = 0; j < 8; j++) acc[i][j] = 0.f;

    for (int k0 = 0; k0 < Kd; k0 += BK) {
        // Load A tile (128 rows x 16 cols), transpose into As[k][m]
#pragma unroll
        for (int l = tid; l < 512; l += 256) {
            int row = l >> 2, c4 = l & 3;
            float4 v = *(const float4*)(A + (size_t)(m0 + row) * Kd + k0 + c4 * 4);
            As[c4 * 4 + 0][row] = v.x;
            As[c4 * 4 + 1][row] = v.y;
            As[c4 * 4 + 2][row] = v.z;
            As[c4 * 4 + 3][row] = v.w;
        }
        // Load B tile (128 n-rows x 16 k-cols), transpose into Bs[k][n]
#pragma unroll
        for (int l = tid; l < 512; l += 256) {
            int row = l >> 2, c4 = l & 3;
            float4 v = *(const float4*)(Bm + (size_t)(n0 + row) * Kd + k0 + c4 * 4);
            Bs[c4 * 4 + 0][row] = v.x;
            Bs[c4 * 4 + 1][row] = v.y;
            Bs[c4 * 4 + 2][row] = v.z;
            Bs[c4 * 4 + 3][row] = v.w;
        }
        __syncthreads();

#pragma unroll
        for (int kk = 0; kk < BK; kk++) {
            float a[8], b[8];
            float4 a0 = *(const float4*)&As[kk][ty * 8];
            float4 a1 = *(const float4*)&As[kk][ty * 8 + 4];
            float4 b0 = *(const float4*)&Bs[kk][tx * 8];
            float4 b1 = *(const float4*)&Bs[kk][tx * 8 + 4];
            a[0]=a0.x; a[1]=a0.y; a[2]=a0.z; a[3]=a0.w;
            a[4]=a1.x; a[5]=a1.y; a[6]=a1.z; a[7]=a1.w;
            b[0]=b0.x; b[1]=b0.y; b[2]=b0.z; b[3]=b0.w;
            b[4]=b1.x; b[5]=b1.y; b[6]=b1.z; b[7]=b1.w;
#pragma unroll
            for (int i = 0; i < 8; i++)
#pragma unroll
                for (int j = 0; j < 8; j++)
                    acc[i][j] = fmaf(a[i], b[j], acc[i][j]);
        }
        __syncthreads();
    }

    // Epilogue
#pragma unroll
    for (int i = 0; i < 8; i++) {
        const int m = m0 + ty * 8 + i;
#pragma unroll
        for (int jv = 0; jv < 2; jv++) {
            const int n = n0 + tx * 8 + jv * 4;
            float4 bv = *(const float4*)(bias + n);
            float4 r;
            r.x = acc[i][jv * 4 + 0] + bv.x;
            r.y = acc[i][jv * 4 + 1] + bv.y;
            r.z = acc[i][jv * 4 + 2] + bv.z;
            r.w = acc[i][jv * 4 + 3] + bv.w;
            if (MODE != 1) {
                *(float4*)(C + (size_t)m * N + n) = r;
            } else {
                // n in [0,3072): which = q/k/v, d = n mod 1024, h = d/64, dh = d%64
                const int which = n >> 10;
                const int d = n & 1023;
                const int h = d >> 6;
                const int dh = d & 63;
                const int b_ = m >> 11;      // m / 2048
                const int s_ = m & 2047;
                float* dst = G_Q + (size_t)which * QKV_ELEMS;
                *(float4*)(dst + (((size_t)(b_ * NHEADS + h) * SEQ + s_) * DHEAD + dh)) = r;
            }
        }
    }
}

// ---------------------------------------------------------------------------
// Causal flash attention, fp32. One block = 64 q rows of one (b,h).
// 64 threads, thread t owns q row (qt*64 + t): q & o in registers (16 float4).
// K/V tiles of 32 rows in SMEM; per-tile scores parked in padded SMEM so the
// j-loops can stay partially unrolled (keeps code size small).
// ---------------------------------------------------------------------------
__global__ __launch_bounds__(64)
void attn_kernel()
{
    const int qt = blockIdx.x;          // 0..31
    const int bh = blockIdx.y;          // 0..31
    const int t  = threadIdx.x;         // 0..63
    const int qrow = qt * 64 + t;

    __shared__ float Ksm[32 * DHEAD];   // 8 KB
    __shared__ float Vsm[32 * DHEAD];   // 8 KB
    __shared__ float Ssm[64 * 33];      // per-thread 32 scores, pad 33 -> conflict-free

    // Load q row (pre-scaled by 1/sqrt(Dh))
    const float* qptr = G_Q + ((size_t)bh * SEQ + qrow) * DHEAD;
    float4 qreg[16];
#pragma unroll
    for (int d = 0; d < 16; d++) {
        float4 v = __ldg((const float4*)qptr + d);
        v.x *= 0.125f; v.y *= 0.125f; v.z *= 0.125f; v.w *= 0.125f;
        qreg[d] = v;
    }

    float4 o4[16];
#pragma unroll
    for (int d = 0; d < 16; d++) o4[d] = make_float4(0.f, 0.f, 0.f, 0.f);
    float mval = -1e30f;
    float lsum = 0.f;

    const float* kbase0 = G_K + (size_t)bh * SEQ * DHEAD;
    const float* vbase0 = G_V + (size_t)bh * SEQ * DHEAD;

    const int nkt = (qt + 1) * 2;       // 32-row k tiles up to & incl. diagonal
    for (int kt = 0; kt < nkt; kt++) {
        const int krow0 = kt * 32;
        // Stage K/V tile: 2048 contiguous floats each = 512 float4
        const float4* ksrc = (const float4*)(kbase0 + (size_t)krow0 * DHEAD);
        const float4* vsrc = (const float4*)(vbase0 + (size_t)krow0 * DHEAD);
#pragma unroll
        for (int l = t; l < 512; l += 64) {
            ((float4*)Ksm)[l] = ksrc[l];
            ((float4*)Vsm)[l] = vsrc[l];
        }
        __syncthreads();

        // Scores for 32 k rows
        float tilemax = -1e30f;
#pragma unroll 4
        for (int j = 0; j < 32; j++) {
            const float4* kr = (const float4*)(Ksm + j * DHEAD);
            float acc = 0.f;
#pragma unroll
            for (int d = 0; d < 16; d++) {
                float4 kv = kr[d];
                acc = fmaf(qreg[d].x, kv.x, acc);
                acc = fmaf(qreg[d].y, kv.y, acc);
                acc = fmaf(qreg[d].z, kv.z, acc);
                acc = fmaf(qreg[d].w, kv.w, acc);
            }
            acc = (krow0 + j <= qrow) ? acc : -1e30f;
            Ssm[t * 33 + j] = acc;
            tilemax = fmaxf(tilemax, acc);
        }

        const float mnew = fmaxf(mval, tilemax);
        const float corr = __expf(mval - mnew);
        lsum *= corr;
#pragma unroll
        for (int d = 0; d < 16; d++) {
            o4[d].x *= corr; o4[d].y *= corr; o4[d].z *= corr; o4[d].w *= corr;
        }

#pragma unroll 4
        for (int j = 0; j < 32; j++) {
            const float p = __expf(Ssm[t * 33 + j] - mnew);
            lsum += p;
            const float4* vr = (const float4*)(Vsm + j * DHEAD);
#pragma unroll
            for (int d = 0; d < 16; d++) {
                float4 vv = vr[d];
                o4[d].x = fmaf(p, vv.x, o4[d].x);
                o4[d].y = fmaf(p, vv.y, o4[d].y);
                o4[d].z = fmaf(p, vv.z, o4[d].z);
                o4[d].w = fmaf(p, vv.w, o4[d].w);
            }
        }
        mval = mnew;
        __syncthreads();
    }

    const float inv = 1.0f / lsum;
    const int b_ = bh >> 4;
    const int h  = bh & 15;
    float* op = G_INTER + ((size_t)b_ * SEQ + qrow) * DMODEL + h * DHEAD;
#pragma unroll
    for (int d = 0; d < 16; d++) {
        float4 r = o4[d];
        r.x *= inv; r.y *= inv; r.z *= inv; r.w *= inv;
        ((float4*)op)[d] = r;
    }
}

// ---------------------------------------------------------------------------
extern "C" void kernel_launch(void* const* d_in, const int* in_sizes, int n_in,
                              void* d_out, int out_size)
{
    const float* res    = (const float*)d_in[0];  // [2,2048,1024]
    const float* W_attn = (const float*)d_in[1];  // [3072,1024]
    const float* b_attn = (const float*)d_in[2];  // [3072]
    const float* W_O    = (const float*)d_in[3];  // [1024,1024]
    const float* b_O    = (const float*)d_in[4];  // [1024]
    float* out = (float*)d_out;                   // [2,2048,1024]

    // 1. QKV projection + fused head-split scatter
    {
        dim3 grid(3 * DMODEL / 128, BATCH * SEQ / 128);   // (24, 32)
        sgemm_nt<1><<<grid, 256>>>(res, W_attn, b_attn, nullptr,
                                   BATCH * SEQ, 3 * DMODEL, DMODEL);
    }
    // 2. Causal attention
    {
        dim3 grid(SEQ / 64, BHD);                          // (32, 32)
        attn_kernel<<<grid, 64>>>();
    }
    // 3. Output projection (A = G_INTER, read device-side; no symbol lookup)
    {
        dim3 grid(DMODEL / 128, BATCH * SEQ / 128);        // (8, 32)
        sgemm_nt<2><<<grid, 256>>>(nullptr, W_O, b_O, out,
                                   BATCH * SEQ, DMODEL, DMODEL);
    }
}

// round 4
// speedup vs baseline: 1.4269x; 1.4269x over previous
#include <cuda_runtime.h>
#include <cstdint>

#define SEQ 2048
#define BATCH 2
#define DMODEL 1024
#define NHEADS 16
#define DHEAD 64
#define BHD (BATCH*NHEADS)

// Single consolidated scratch buffer (allocation-free rule: __device__ global).
// Layout: [q | k | v | inter], each BHD*SEQ*DHEAD = 4M floats (16 MB).
#define QKV_ELEMS (BHD*SEQ*DHEAD)       // 4,194,304
__device__ float g_scratch[4 * QKV_ELEMS];
#define G_Q     (g_scratch)
#define G_K     (g_scratch + QKV_ELEMS)
#define G_V     (g_scratch + 2*QKV_ELEMS)
#define G_INTER (g_scratch + 3*QKV_ELEMS)   // viewed as [B,S,D]

// ---------------------------------------------------------------------------
// SGEMM NT: C[M,N] = A[M,K] * Bm[N,K]^T + bias[N]   (unchanged from R3)
// MODE 0: plain write to C, A from param.
// MODE 1: A from param, scatter into q/k/v ([B,H,S,Dh]).
// MODE 2: A = G_INTER (device global), plain write to C.
// ---------------------------------------------------------------------------
template<int MODE>
__global__ __launch_bounds__(256)
void sgemm_nt(const float* __restrict__ Ap, const float* __restrict__ Bm,
              const float* __restrict__ bias, float* __restrict__ C,
              int M, int N, int Kd)
{
    constexpr int BM = 128, BN = 128, BK = 16;
    __shared__ float As[BK][BM + 4];
    __shared__ float Bs[BK][BN + 4];

    const float* A = (MODE == 2) ? G_INTER : Ap;

    const int tid = threadIdx.x;
    const int tx = tid & 15;
    const int ty = tid >> 4;
    const int m0 = blockIdx.y * BM;
    const int n0 = blockIdx.x * BN;

    float acc[8][8];
#pragma unroll
    for (int i = 0; i < 8; i++)
#pragma unroll
        for (int j = 0; j < 8; j++) acc[i][j] = 0.f;

    for (int k0 = 0; k0 < Kd; k0 += BK) {
#pragma unroll
        for (int l = tid; l < 512; l += 256) {
            int row = l >> 2, c4 = l & 3;
            float4 v = *(const float4*)(A + (size_t)(m0 + row) * Kd + k0 + c4 * 4);
            As[c4 * 4 + 0][row] = v.x;
            As[c4 * 4 + 1][row] = v.y;
            As[c4 * 4 + 2][row] = v.z;
            As[c4 * 4 + 3][row] = v.w;
        }
#pragma unroll
        for (int l = tid; l < 512; l += 256) {
            int row = l >> 2, c4 = l & 3;
            float4 v = *(const float4*)(Bm + (size_t)(n0 + row) * Kd + k0 + c4 * 4);
            Bs[c4 * 4 + 0][row] = v.x;
            Bs[c4 * 4 + 1][row] = v.y;
            Bs[c4 * 4 + 2][row] = v.z;
            Bs[c4 * 4 + 3][row] = v.w;
        }
        __syncthreads();

#pragma unroll
        for (int kk = 0; kk < BK; kk++) {
            float a[8], b[8];
            float4 a0 = *(const float4*)&As[kk][ty * 8];
            float4 a1 = *(const float4*)&As[kk][ty * 8 + 4];
            float4 b0 = *(const float4*)&Bs[kk][tx * 8];
            float4 b1 = *(const float4*)&Bs[kk][tx * 8 + 4];
            a[0]=a0.x; a[1]=a0.y; a[2]=a0.z; a[3]=a0.w;
            a[4]=a1.x; a[5]=a1.y; a[6]=a1.z; a[7]=a1.w;
            b[0]=b0.x; b[1]=b0.y; b[2]=b0.z; b[3]=b0.w;
            b[4]=b1.x; b[5]=b1.y; b[6]=b1.z; b[7]=b1.w;
#pragma unroll
            for (int i = 0; i < 8; i++)
#pragma unroll
                for (int j = 0; j < 8; j++)
                    acc[i][j] = fmaf(a[i], b[j], acc[i][j]);
        }
        __syncthreads();
    }

#pragma unroll
    for (int i = 0; i < 8; i++) {
        const int m = m0 + ty * 8 + i;
#pragma unroll
        for (int jv = 0; jv < 2; jv++) {
            const int n = n0 + tx * 8 + jv * 4;
            float4 bv = *(const float4*)(bias + n);
            float4 r;
            r.x = acc[i][jv * 4 + 0] + bv.x;
            r.y = acc[i][jv * 4 + 1] + bv.y;
            r.z = acc[i][jv * 4 + 2] + bv.z;
            r.w = acc[i][jv * 4 + 3] + bv.w;
            if (MODE != 1) {
                *(float4*)(C + (size_t)m * N + n) = r;
            } else {
                const int which = n >> 10;
                const int d = n & 1023;
                const int h = d >> 6;
                const int dh = d & 63;
                const int b_ = m >> 11;
                const int s_ = m & 2047;
                float* dst = G_Q + (size_t)which * QKV_ELEMS;
                *(float4*)(dst + (((size_t)(b_ * NHEADS + h) * SEQ + s_) * DHEAD + dh)) = r;
            }
        }
    }
}

// ---------------------------------------------------------------------------
// Register-tiled causal flash attention (fp32).
// Block: 256 threads = 16(ty, m-dim) x 16(tx, j/d-dim). Q-tile 128 rows,
// K-tile 64 rows. Two register-tiled GEMMs per K-tile:
//   S[128][64] = Qs^T-layout GEMM (8x4 per-thread tile)
//   O[128][64] += P[128][64] * V[64][64]  (P through SMEM, transposed)
// Online softmax row stats via shfl over 16-lane tx groups.
// SMEM (dynamic, 100 KB): Qs[64][132] d-major | Ks[64][68] d-major |
//                         Vs[64][68] j-major  | Ps[64][132] j-major
// ---------------------------------------------------------------------------
#define QS_STRIDE 132
#define KS_STRIDE 68
#define VS_STRIDE 68
#define PS_STRIDE 132
#define ATTN_SMEM_BYTES ((64*QS_STRIDE + 64*KS_STRIDE + 64*VS_STRIDE + 64*PS_STRIDE) * 4)

__global__ __launch_bounds__(256)
void attn_kernel()
{
    extern __shared__ float sm[];
    float* Qs = sm;                          // [64][132]  Qs[d][m]
    float* Ks = Qs + 64 * QS_STRIDE;         // [64][68]   Ks[d][j]
    float* Vs = Ks + 64 * KS_STRIDE;         // [64][68]   Vs[j][d]
    float* Ps = Vs + 64 * VS_STRIDE;         // [64][132]  Ps[j][m]

    const int bh = blockIdx.x;                       // 0..31
    const int qt = (int)(gridDim.y - 1 - blockIdx.y); // descending: big blocks first
    const int tid = threadIdx.x;
    const int tx = tid & 15;
    const int ty = tid >> 4;
    const int q0 = qt * 128;

    const float* Qg = G_Q + ((size_t)bh * SEQ + q0) * DHEAD;
    const float* Kg = G_K + (size_t)bh * SEQ * DHEAD;
    const float* Vg = G_V + (size_t)bh * SEQ * DHEAD;

    // Stage Q tile transposed + pre-scaled by 1/sqrt(Dh).
    // thread: row r = tid/2 (0..127), d-half = (tid&1)*32
    {
        const int r = tid >> 1;
        const int dh0 = (tid & 1) * 32;
        const float4* src = (const float4*)(Qg + (size_t)r * DHEAD + dh0);
#pragma unroll
        for (int c = 0; c < 8; c++) {
            float4 v = src[c];
            const int d = dh0 + c * 4;
            Qs[(d + 0) * QS_STRIDE + r] = v.x * 0.125f;
            Qs[(d + 1) * QS_STRIDE + r] = v.y * 0.125f;
            Qs[(d + 2) * QS_STRIDE + r] = v.z * 0.125f;
            Qs[(d + 3) * QS_STRIDE + r] = v.w * 0.125f;
        }
    }

    float o_acc[8][4];
#pragma unroll
    for (int i = 0; i < 8; i++)
#pragma unroll
        for (int d = 0; d < 4; d++) o_acc[i][d] = 0.f;
    float m_run[8], l_run[8];
#pragma unroll
    for (int i = 0; i < 8; i++) { m_run[i] = -1e30f; l_run[i] = 0.f; }

    const int nkt = 2 * qt + 2;
    for (int kt = 0; kt < nkt; kt++) {
        const int k0 = kt * 64;

        // Stage K transposed: thread row j = tid/4, d-chunk = (tid&3)*16
        {
            const int j = tid >> 2;
            const int d0 = (tid & 3) * 16;
            const float4* src = (const float4*)(Kg + (size_t)(k0 + j) * DHEAD + d0);
#pragma unroll
            for (int c = 0; c < 4; c++) {
                float4 v = src[c];
                const int d = d0 + c * 4;
                Ks[(d + 0) * KS_STRIDE + j] = v.x;
                Ks[(d + 1) * KS_STRIDE + j] = v.y;
                Ks[(d + 2) * KS_STRIDE + j] = v.z;
                Ks[(d + 3) * KS_STRIDE + j] = v.w;
            }
        }
        // Stage V direct (j-major)
        {
            const int j = tid >> 2;
            const int d0 = (tid & 3) * 16;
            const float4* src = (const float4*)(Vg + (size_t)(k0 + j) * DHEAD + d0);
            float4* dst = (float4*)(Vs + j * VS_STRIDE + d0);
#pragma unroll
            for (int c = 0; c < 4; c++) dst[c] = src[c];
        }
        __syncthreads();

        // ---- S = Q*K^T (8x4 per-thread tile) ----
        float s[8][4];
#pragma unroll
        for (int i = 0; i < 8; i++)
#pragma unroll
            for (int j = 0; j < 4; j++) s[i][j] = 0.f;

#pragma unroll 8
        for (int d = 0; d < 64; d++) {
            float4 a0 = *(const float4*)&Qs[d * QS_STRIDE + ty * 8];
            float4 a1 = *(const float4*)&Qs[d * QS_STRIDE + ty * 8 + 4];
            float4 b  = *(const float4*)&Ks[d * KS_STRIDE + tx * 4];
            float a[8] = {a0.x, a0.y, a0.z, a0.w, a1.x, a1.y, a1.z, a1.w};
#pragma unroll
            for (int i = 0; i < 8; i++) {
                s[i][0] = fmaf(a[i], b.x, s[i][0]);
                s[i][1] = fmaf(a[i], b.y, s[i][1]);
                s[i][2] = fmaf(a[i], b.z, s[i][2]);
                s[i][3] = fmaf(a[i], b.w, s[i][3]);
            }
        }

        // ---- causal mask (only last two tiles touch the diagonal) ----
        if (kt >= 2 * qt) {
#pragma unroll
            for (int i = 0; i < 8; i++) {
                const int qr = q0 + ty * 8 + i;
#pragma unroll
                for (int j = 0; j < 4; j++) {
                    if (k0 + tx * 4 + j > qr) s[i][j] = -1e30f;
                }
            }
        }

        // ---- online softmax per row (reduce across 16 tx lanes) ----
        float corr[8], mnew_a[8];
#pragma unroll
        for (int i = 0; i < 8; i++) {
            float tmax = fmaxf(fmaxf(s[i][0], s[i][1]), fmaxf(s[i][2], s[i][3]));
#pragma unroll
            for (int w = 1; w < 16; w <<= 1)
                tmax = fmaxf(tmax, __shfl_xor_sync(0xffffffffu, tmax, w));
            const float mnew = fmaxf(m_run[i], tmax);
            mnew_a[i] = mnew;
            corr[i] = __expf(m_run[i] - mnew);
            float psum = 0.f;
#pragma unroll
            for (int j = 0; j < 4; j++) {
                const float p = __expf(s[i][j] - mnew);
                s[i][j] = p;
                psum += p;
            }
#pragma unroll
            for (int w = 1; w < 16; w <<= 1)
                psum += __shfl_xor_sync(0xffffffffu, psum, w);
            l_run[i] = l_run[i] * corr[i] + psum;
            m_run[i] = mnew;
        }

        // rescale O accumulators
#pragma unroll
        for (int i = 0; i < 8; i++) {
            o_acc[i][0] *= corr[i];
            o_acc[i][1] *= corr[i];
            o_acc[i][2] *= corr[i];
            o_acc[i][3] *= corr[i];
        }

        // ---- write P transposed: Ps[j][m], vectorized over m ----
        __syncthreads();   // everyone done reading Ks/Qs region state for this tile's S
#pragma unroll
        for (int j = 0; j < 4; j++) {
            const int jr = (tx * 4 + j) * PS_STRIDE + ty * 8;
            *(float4*)&Ps[jr]     = make_float4(s[0][j], s[1][j], s[2][j], s[3][j]);
            *(float4*)&Ps[jr + 4] = make_float4(s[4][j], s[5][j], s[6][j], s[7][j]);
        }
        __syncthreads();

        // ---- O += P * V (8x4 per-thread tile) ----
#pragma unroll 8
        for (int j = 0; j < 64; j++) {
            float4 a0 = *(const float4*)&Ps[j * PS_STRIDE + ty * 8];
            float4 a1 = *(const float4*)&Ps[j * PS_STRIDE + ty * 8 + 4];
            float4 b  = *(const float4*)&Vs[j * VS_STRIDE + tx * 4];
            float a[8] = {a0.x, a0.y, a0.z, a0.w, a1.x, a1.y, a1.z, a1.w};
#pragma unroll
            for (int i = 0; i < 8; i++) {
                o_acc[i][0] = fmaf(a[i], b.x, o_acc[i][0]);
                o_acc[i][1] = fmaf(a[i], b.y, o_acc[i][1]);
                o_acc[i][2] = fmaf(a[i], b.z, o_acc[i][2]);
                o_acc[i][3] = fmaf(a[i], b.w, o_acc[i][3]);
            }
        }
        __syncthreads();   // protect Ks/Vs/Ps before next tile's staging
    }

    // ---- epilogue: normalize and write to G_INTER [B,S,D] ----
    const int b_ = bh >> 4;
    const int h  = bh & 15;
#pragma unroll
    for (int i = 0; i < 8; i++) {
        const float inv = 1.0f / l_run[i];
        const int qr = q0 + ty * 8 + i;
        float4 r;
        r.x = o_acc[i][0] * inv;
        r.y = o_acc[i][1] * inv;
        r.z = o_acc[i][2] * inv;
        r.w = o_acc[i][3] * inv;
        *(float4*)(G_INTER + ((size_t)b_ * SEQ + qr) * DMODEL + h * DHEAD + tx * 4) = r;
    }
}

// ---------------------------------------------------------------------------
extern "C" void kernel_launch(void* const* d_in, const int* in_sizes, int n_in,
                              void* d_out, int out_size)
{
    const float* res    = (const float*)d_in[0];  // [2,2048,1024]
    const float* W_attn = (const float*)d_in[1];  // [3072,1024]
    const float* b_attn = (const float*)d_in[2];  // [3072]
    const float* W_O    = (const float*)d_in[3];  // [1024,1024]
    const float* b_O    = (const float*)d_in[4];  // [1024]
    float* out = (float*)d_out;                   // [2,2048,1024]

    // 1. QKV projection + fused head-split scatter
    {
        dim3 grid(3 * DMODEL / 128, BATCH * SEQ / 128);   // (24, 32)
        sgemm_nt<1><<<grid, 256>>>(res, W_attn, b_attn, nullptr,
                                   BATCH * SEQ, 3 * DMODEL, DMODEL);
    }
    // 2. Causal attention (register-tiled flash)
    {
        cudaFuncSetAttribute(attn_kernel,
                             cudaFuncAttributeMaxDynamicSharedMemorySize,
                             ATTN_SMEM_BYTES);
        dim3 grid(BHD, SEQ / 128);                         // (32, 16)
        attn_kernel<<<grid, 256, ATTN_SMEM_BYTES>>>();
    }
    // 3. Output projection (A = G_INTER, read device-side)
    {
        dim3 grid(DMODEL / 128, BATCH * SEQ / 128);        // (8, 32)
        sgemm_nt<2><<<grid, 256>>>(nullptr, W_O, b_O, out,
                                   BATCH * SEQ, DMODEL, DMODEL);
    }
}

// round 7
// speedup vs baseline: 2.2522x; 1.5784x over previous
#include <cuda_runtime.h>
#include <cuda_bf16.h>
#include <cstdint>

#define SEQ 2048
#define BATCH 2
#define DMODEL 1024
#define NHEADS 16
#define DHEAD 64
#define BHD (BATCH*NHEADS)

// Single consolidated scratch buffer (allocation-free rule: __device__ global).
#define QKV_ELEMS (BHD*SEQ*DHEAD)       // 4,194,304
__device__ float g_scratch[4 * QKV_ELEMS];
#define G_Q     (g_scratch)
#define G_K     (g_scratch + QKV_ELEMS)
#define G_V     (g_scratch + 2*QKV_ELEMS)
#define G_INTER (g_scratch + 3*QKV_ELEMS)   // viewed as [B,S,D]

// ---------------------------------------------------------------------------
// Warp-level bf16 MMA (m16n8k16), fp32 accumulate. Supported on sm_80+,
// compiles for bare sm_100 target (tcgen05 is NOT available in this harness).
// ---------------------------------------------------------------------------
__device__ __forceinline__ void mma_bf16(float c[4],
    uint32_t a0, uint32_t a1, uint32_t a2, uint32_t a3,
    uint32_t b0, uint32_t b1)
{
    asm volatile(
        "mma.sync.aligned.m16n8k16.row.col.f32.bf16.bf16.f32 "
        "{%0,%1,%2,%3}, {%4,%5,%6,%7}, {%8,%9}, {%0,%1,%2,%3};"
        : "+f"(c[0]), "+f"(c[1]), "+f"(c[2]), "+f"(c[3])
        : "r"(a0), "r"(a1), "r"(a2), "r"(a3), "r"(b0), "r"(b1));
}

// ---------------------------------------------------------------------------
// Tensor-core bf16 3-pass GEMM: C[M,N] = A[M,K] * Bm[N,K]^T + bias[N]
// fp32 inputs are split A = Ahi + Alo (bf16 each); D = Ahi*Bhi + Ahi*Blo +
// Alo*Bhi (lo*lo term ~2^-16 relative, dropped). rel err ~1e-5.
// CTA tile 128x128, K-chunk 32. 8 warps: 4(m) x 2(n), warp tile 32x64.
// SMEM tiles [128][LDA] bf16, LDA=40 padding -> conflict-free fragment LDS.
// MODE 0: plain write, A from param. MODE 1: scatter q/k/v. MODE 2: A = G_INTER.
// ---------------------------------------------------------------------------
#define LDA 40

template<int MODE>
__global__ __launch_bounds__(256, 2)
void tc_gemm(const float* __restrict__ Ap, const float* __restrict__ Bm,
             const float* __restrict__ bias, float* __restrict__ C,
             int M, int N, int Kd)
{
    __shared__ __align__(16) uint16_t Ahi[128 * LDA];
    __shared__ __align__(16) uint16_t Alo[128 * LDA];
    __shared__ __align__(16) uint16_t Bhi[128 * LDA];
    __shared__ __align__(16) uint16_t Blo[128 * LDA];

    const float* A = (MODE == 2) ? G_INTER : Ap;
    const int tid  = threadIdx.x;
    const int wid  = tid >> 5;
    const int lane = tid & 31;
    const int m0 = blockIdx.y * 128;
    const int n0 = blockIdx.x * 128;
    const int wm = (wid & 3) * 32;     // warp m offset in tile
    const int wn = (wid >> 2) * 64;    // warp n offset in tile

    float c[2][8][4];
#pragma unroll
    for (int mf = 0; mf < 2; mf++)
#pragma unroll
        for (int nf = 0; nf < 8; nf++)
#pragma unroll
            for (int e = 0; e < 4; e++) c[mf][nf][e] = 0.f;

    const float* Abase = A  + (size_t)m0 * Kd;
    const float* Bbase = Bm + (size_t)n0 * Kd;

    const int nchunk = Kd >> 5;        // K-chunks of 32
    for (int ch = 0; ch < nchunk; ch++) {
        const int k0 = ch * 32;
        __syncthreads();   // previous MMA phase done reading smem

        // ---- stage: fp32 -> bf16 hi/lo, both tiles ----
#pragma unroll
        for (int i = 0; i < 4; i++) {
            const int l = tid + i * 256;         // 0..1023
            const int row = l >> 3;
            const int c4  = l & 7;               // float4 index within 32 cols
            // A tile
            {
                float4 v = *(const float4*)(Abase + (size_t)row * Kd + k0 + c4 * 4);
                __nv_bfloat162 h01 = __floats2bfloat162_rn(v.x, v.y);
                __nv_bfloat162 h23 = __floats2bfloat162_rn(v.z, v.w);
                float rx = v.x - __bfloat162float(h01.x);
                float ry = v.y - __bfloat162float(h01.y);
                float rz = v.z - __bfloat162float(h23.x);
                float rw = v.w - __bfloat162float(h23.y);
                __nv_bfloat162 l01 = __floats2bfloat162_rn(rx, ry);
                __nv_bfloat162 l23 = __floats2bfloat162_rn(rz, rw);
                uint2 hh = make_uint2(*(uint32_t*)&h01, *(uint32_t*)&h23);
                uint2 ll = make_uint2(*(uint32_t*)&l01, *(uint32_t*)&l23);
                *(uint2*)&Ahi[row * LDA + c4 * 4] = hh;
                *(uint2*)&Alo[row * LDA + c4 * 4] = ll;
            }
            // B tile
            {
                float4 v = *(const float4*)(Bbase + (size_t)row * Kd + k0 + c4 * 4);
                __nv_bfloat162 h01 = __floats2bfloat162_rn(v.x, v.y);
                __nv_bfloat162 h23 = __floats2bfloat162_rn(v.z, v.w);
                float rx = v.x - __bfloat162float(h01.x);
                float ry = v.y - __bfloat162float(h01.y);
                float rz = v.z - __bfloat162float(h23.x);
                float rw = v.w - __bfloat162float(h23.y);
                __nv_bfloat162 l01 = __floats2bfloat162_rn(rx, ry);
                __nv_bfloat162 l23 = __floats2bfloat162_rn(rz, rw);
                uint2 hh = make_uint2(*(uint32_t*)&h01, *(uint32_t*)&h23);
                uint2 ll = make_uint2(*(uint32_t*)&l01, *(uint32_t*)&l23);
                *(uint2*)&Bhi[row * LDA + c4 * 4] = hh;
                *(uint2*)&Blo[row * LDA + c4 * 4] = ll;
            }
        }
        __syncthreads();

        // ---- MMA phase: 2 k-steps of 16 ----
#pragma unroll
        for (int ks = 0; ks < 2; ks++) {
            const int kc = ks * 16;
            const int arow = wm + (lane >> 2);
            const int acol = kc + (lane & 3) * 2;

            uint32_t ah[2][4], al[2][4];
#pragma unroll
            for (int mf = 0; mf < 2; mf++) {
                const int r = arow + mf * 16;
                ah[mf][0] = *(const uint32_t*)&Ahi[(r    ) * LDA + acol    ];
                ah[mf][1] = *(const uint32_t*)&Ahi[(r + 8) * LDA + acol    ];
                ah[mf][2] = *(const uint32_t*)&Ahi[(r    ) * LDA + acol + 8];
                ah[mf][3] = *(const uint32_t*)&Ahi[(r + 8) * LDA + acol + 8];
                al[mf][0] = *(const uint32_t*)&Alo[(r    ) * LDA + acol    ];
                al[mf][1] = *(const uint32_t*)&Alo[(r + 8) * LDA + acol    ];
                al[mf][2] = *(const uint32_t*)&Alo[(r    ) * LDA + acol + 8];
                al[mf][3] = *(const uint32_t*)&Alo[(r + 8) * LDA + acol + 8];
            }

#pragma unroll
            for (int nf = 0; nf < 8; nf++) {
                const int nrow = wn + nf * 8 + (lane >> 2);
                const int bcol = kc + (lane & 3) * 2;
                uint32_t bh0 = *(const uint32_t*)&Bhi[nrow * LDA + bcol    ];
                uint32_t bh1 = *(const uint32_t*)&Bhi[nrow * LDA + bcol + 8];
                uint32_t bl0 = *(const uint32_t*)&Blo[nrow * LDA + bcol    ];
                uint32_t bl1 = *(const uint32_t*)&Blo[nrow * LDA + bcol + 8];
#pragma unroll
                for (int mf = 0; mf < 2; mf++) {
                    mma_bf16(c[mf][nf], ah[mf][0], ah[mf][1], ah[mf][2], ah[mf][3], bh0, bh1);
                    mma_bf16(c[mf][nf], ah[mf][0], ah[mf][1], ah[mf][2], ah[mf][3], bl0, bl1);
                    mma_bf16(c[mf][nf], al[mf][0], al[mf][1], al[mf][2], al[mf][3], bh0, bh1);
                }
            }
        }
    }

    // ---- epilogue: bias + store (float2 pairs per fragment row) ----
#pragma unroll
    for (int mf = 0; mf < 2; mf++) {
#pragma unroll
        for (int nf = 0; nf < 8; nf++) {
            const int n = n0 + wn + nf * 8 + (lane & 3) * 2;
            const float2 bv = *(const float2*)(bias + n);
#pragma unroll
            for (int half = 0; half < 2; half++) {
                const int m = m0 + wm + mf * 16 + (lane >> 2) + half * 8;
                float2 r;
                r.x = c[mf][nf][half * 2 + 0] + bv.x;
                r.y = c[mf][nf][half * 2 + 1] + bv.y;
                if (MODE != 1) {
                    *(float2*)(C + (size_t)m * N + n) = r;
                } else {
                    const int which = n >> 10;
                    const int d = n & 1023;
                    const int h = d >> 6;
                    const int dh = d & 63;
                    const int b_ = m >> 11;
                    const int s_ = m & 2047;
                    float* dst = G_Q + (size_t)which * QKV_ELEMS;
                    *(float2*)(dst + (((size_t)(b_ * NHEADS + h) * SEQ + s_) * DHEAD + dh)) = r;
                }
            }
        }
    }
}

// ---------------------------------------------------------------------------
// Register-tiled causal flash attention (fp32) — unchanged from R4.
// ---------------------------------------------------------------------------
#define QS_STRIDE 132
#define KS_STRIDE 68
#define VS_STRIDE 68
#define PS_STRIDE 132
#define ATTN_SMEM_BYTES ((64*QS_STRIDE + 64*KS_STRIDE + 64*VS_STRIDE + 64*PS_STRIDE) * 4)

__global__ __launch_bounds__(256)
void attn_kernel()
{
    extern __shared__ float sm[];
    float* Qs = sm;                          // [64][132]  Qs[d][m]
    float* Ks = Qs + 64 * QS_STRIDE;         // [64][68]   Ks[d][j]
    float* Vs = Ks + 64 * KS_STRIDE;         // [64][68]   Vs[j][d]
    float* Ps = Vs + 64 * VS_STRIDE;         // [64][132]  Ps[j][m]

    const int bh = blockIdx.x;
    const int qt = (int)(gridDim.y - 1 - blockIdx.y);
    const int tid = threadIdx.x;
    const int tx = tid & 15;
    const int ty = tid >> 4;
    const int q0 = qt * 128;

    const float* Qg = G_Q + ((size_t)bh * SEQ + q0) * DHEAD;
    const float* Kg = G_K + (size_t)bh * SEQ * DHEAD;
    const float* Vg = G_V + (size_t)bh * SEQ * DHEAD;

    {
        const int r = tid >> 1;
        const int dh0 = (tid & 1) * 32;
        const float4* src = (const float4*)(Qg + (size_t)r * DHEAD + dh0);
#pragma unroll
        for (int c = 0; c < 8; c++) {
            float4 v = src[c];
            const int d = dh0 + c * 4;
            Qs[(d + 0) * QS_STRIDE + r] = v.x * 0.125f;
            Qs[(d + 1) * QS_STRIDE + r] = v.y * 0.125f;
            Qs[(d + 2) * QS_STRIDE + r] = v.z * 0.125f;
            Qs[(d + 3) * QS_STRIDE + r] = v.w * 0.125f;
        }
    }

    float o_acc[8][4];
#pragma unroll
    for (int i = 0; i < 8; i++)
#pragma unroll
        for (int d = 0; d < 4; d++) o_acc[i][d] = 0.f;
    float m_run[8], l_run[8];
#pragma unroll
    for (int i = 0; i < 8; i++) { m_run[i] = -1e30f; l_run[i] = 0.f; }

    const int nkt = 2 * qt + 2;
    for (int kt = 0; kt < nkt; kt++) {
        const int k0 = kt * 64;

        {
            const int j = tid >> 2;
            const int d0 = (tid & 3) * 16;
            const float4* src = (const float4*)(Kg + (size_t)(k0 + j) * DHEAD + d0);
#pragma unroll
            for (int c = 0; c < 4; c++) {
                float4 v = src[c];
                const int d = d0 + c * 4;
                Ks[(d + 0) * KS_STRIDE + j] = v.x;
                Ks[(d + 1) * KS_STRIDE + j] = v.y;
                Ks[(d + 2) * KS_STRIDE + j] = v.z;
                Ks[(d + 3) * KS_STRIDE + j] = v.w;
            }
        }
        {
            const int j = tid >> 2;
            const int d0 = (tid & 3) * 16;
            const float4* src = (const float4*)(Vg + (size_t)(k0 + j) * DHEAD + d0);
            float4* dst = (float4*)(Vs + j * VS_STRIDE + d0);
#pragma unroll
            for (int c = 0; c < 4; c++) dst[c] = src[c];
        }
        __syncthreads();

        float s[8][4];
#pragma unroll
        for (int i = 0; i < 8; i++)
#pragma unroll
            for (int j = 0; j < 4; j++) s[i][j] = 0.f;

#pragma unroll 8
        for (int d = 0; d < 64; d++) {
            float4 a0 = *(const float4*)&Qs[d * QS_STRIDE + ty * 8];
            float4 a1 = *(const float4*)&Qs[d * QS_STRIDE + ty * 8 + 4];
            float4 b  = *(const float4*)&Ks[d * KS_STRIDE + tx * 4];
            float a[8] = {a0.x, a0.y, a0.z, a0.w, a1.x, a1.y, a1.z, a1.w};
#pragma unroll
            for (int i = 0; i < 8; i++) {
                s[i][0] = fmaf(a[i], b.x, s[i][0]);
                s[i][1] = fmaf(a[i], b.y, s[i][1]);
                s[i][2] = fmaf(a[i], b.z, s[i][2]);
                s[i][3] = fmaf(a[i], b.w, s[i][3]);
            }
        }

        if (kt >= 2 * qt) {
#pragma unroll
            for (int i = 0; i < 8; i++) {
                const int qr = q0 + ty * 8 + i;
#pragma unroll
                for (int j = 0; j < 4; j++) {
                    if (k0 + tx * 4 + j > qr) s[i][j] = -1e30f;
                }
            }
        }

        float corr[8];
#pragma unroll
        for (int i = 0; i < 8; i++) {
            float tmax = fmaxf(fmaxf(s[i][0], s[i][1]), fmaxf(s[i][2], s[i][3]));
#pragma unroll
            for (int w = 1; w < 16; w <<= 1)
                tmax = fmaxf(tmax, __shfl_xor_sync(0xffffffffu, tmax, w));
            const float mnew = fmaxf(m_run[i], tmax);
            corr[i] = __expf(m_run[i] - mnew);
            float psum = 0.f;
#pragma unroll
            for (int j = 0; j < 4; j++) {
                const float p = __expf(s[i][j] - mnew);
                s[i][j] = p;
                psum += p;
            }
#pragma unroll
            for (int w = 1; w < 16; w <<= 1)
                psum += __shfl_xor_sync(0xffffffffu, psum, w);
            l_run[i] = l_run[i] * corr[i] + psum;
            m_run[i] = mnew;
        }

#pragma unroll
        for (int i = 0; i < 8; i++) {
            o_acc[i][0] *= corr[i];
            o_acc[i][1] *= corr[i];
            o_acc[i][2] *= corr[i];
            o_acc[i][3] *= corr[i];
        }

        __syncthreads();
#pragma unroll
        for (int j = 0; j < 4; j++) {
            const int jr = (tx * 4 + j) * PS_STRIDE + ty * 8;
            *(float4*)&Ps[jr]     = make_float4(s[0][j], s[1][j], s[2][j], s[3][j]);
            *(float4*)&Ps[jr + 4] = make_float4(s[4][j], s[5][j], s[6][j], s[7][j]);
        }
        __syncthreads();

#pragma unroll 8
        for (int j = 0; j < 64; j++) {
            float4 a0 = *(const float4*)&Ps[j * PS_STRIDE + ty * 8];
            float4 a1 = *(const float4*)&Ps[j * PS_STRIDE + ty * 8 + 4];
            float4 b  = *(const float4*)&Vs[j * VS_STRIDE + tx * 4];
            float a[8] = {a0.x, a0.y, a0.z, a0.w, a1.x, a1.y, a1.z, a1.w};
#pragma unroll
            for (int i = 0; i < 8; i++) {
                o_acc[i][0] = fmaf(a[i], b.x, o_acc[i][0]);
                o_acc[i][1] = fmaf(a[i], b.y, o_acc[i][1]);
                o_acc[i][2] = fmaf(a[i], b.z, o_acc[i][2]);
                o_acc[i][3] = fmaf(a[i], b.w, o_acc[i][3]);
            }
        }
        __syncthreads();
    }

    const int b_ = bh >> 4;
    const int h  = bh & 15;
#pragma unroll
    for (int i = 0; i < 8; i++) {
        const float inv = 1.0f / l_run[i];
        const int qr = q0 + ty * 8 + i;
        float4 r;
        r.x = o_acc[i][0] * inv;
        r.y = o_acc[i][1] * inv;
        r.z = o_acc[i][2] * inv;
        r.w = o_acc[i][3] * inv;
        *(float4*)(G_INTER + ((size_t)b_ * SEQ + qr) * DMODEL + h * DHEAD + tx * 4) = r;
    }
}

// ---------------------------------------------------------------------------
extern "C" void kernel_launch(void* const* d_in, const int* in_sizes, int n_in,
                              void* d_out, int out_size)
{
    const float* res    = (const float*)d_in[0];  // [2,2048,1024]
    const float* W_attn = (const float*)d_in[1];  // [3072,1024]
    const float* b_attn = (const float*)d_in[2];  // [3072]
    const float* W_O    = (const float*)d_in[3];  // [1024,1024]
    const float* b_O    = (const float*)d_in[4];  // [1024]
    float* out = (float*)d_out;                   // [2,2048,1024]

    cudaFuncSetAttribute(attn_kernel, cudaFuncAttributeMaxDynamicSharedMemorySize,
                         ATTN_SMEM_BYTES);

    // 1. QKV projection (bf16 3-pass mma.sync) + fused head-split scatter
    {
        dim3 grid(3 * DMODEL / 128, BATCH * SEQ / 128);   // (24, 32)
        tc_gemm<1><<<grid, 256>>>(res, W_attn, b_attn, nullptr,
                                  BATCH * SEQ, 3 * DMODEL, DMODEL);
    }
    // 2. Causal attention (register-tiled flash, fp32)
    {
        dim3 grid(BHD, SEQ / 128);                         // (32, 16)
        attn_kernel<<<grid, 256, ATTN_SMEM_BYTES>>>();
    }
    // 3. Output projection (bf16 3-pass mma.sync, A = G_INTER — MODE 2!)
    {
        dim3 grid(DMODEL / 128, BATCH * SEQ / 128);        // (8, 32)
        tc_gemm<2><<<grid, 256>>>(nullptr, W_O, b_O, out,
                                  BATCH * SEQ, DMODEL, DMODEL);
    }
}

// round 8
// speedup vs baseline: 3.6407x; 1.6165x over previous
#include <cuda_runtime.h>
#include <cuda_bf16.h>
#include <cstdint>

#define SEQ 2048
#define BATCH 2
#define DMODEL 1024
#define NHEADS 16
#define DHEAD 64
#define BHD (BATCH*NHEADS)

// Single consolidated scratch buffer (allocation-free rule: __device__ global).
// 64 MB total. First 3 fp32 regions reinterpreted as six bf16 arrays (8 MB each):
//   qhi qlo khi klo : [B*H, SEQ, DHEAD] bf16
//   vhi vlo         : [B*H, DHEAD, SEQ] bf16 (pre-transposed for PV B operand)
// Fourth region: G_INTER fp32 [B, S, D].
#define QKV_ELEMS (BHD*SEQ*DHEAD)       // 4,194,304
__device__ float g_scratch[4 * QKV_ELEMS];
#define BF_BASE ((__nv_bfloat16*)g_scratch)
#define G_QHI (BF_BASE)
#define G_QLO (BF_BASE + 1*QKV_ELEMS)
#define G_KHI (BF_BASE + 2*QKV_ELEMS)
#define G_KLO (BF_BASE + 3*QKV_ELEMS)
#define G_VHI (BF_BASE + 4*QKV_ELEMS)
#define G_VLO (BF_BASE + 5*QKV_ELEMS)
#define G_INTER (g_scratch + 3*QKV_ELEMS)   // fp32 [B,S,D]

// ---------------------------------------------------------------------------
// Warp-level bf16 MMA (m16n8k16), fp32 accumulate.
// ---------------------------------------------------------------------------
__device__ __forceinline__ void mma_bf16(float c[4],
    uint32_t a0, uint32_t a1, uint32_t a2, uint32_t a3,
    uint32_t b0, uint32_t b1)
{
    asm volatile(
        "mma.sync.aligned.m16n8k16.row.col.f32.bf16.bf16.f32 "
        "{%0,%1,%2,%3}, {%4,%5,%6,%7}, {%8,%9}, {%0,%1,%2,%3};"
        : "+f"(c[0]), "+f"(c[1]), "+f"(c[2]), "+f"(c[3])
        : "r"(a0), "r"(a1), "r"(a2), "r"(a3), "r"(b0), "r"(b1));
}

__device__ __forceinline__ void pack_hilo(float p0, float p1,
                                          uint32_t& hi, uint32_t& lo)
{
    __nv_bfloat162 h = __floats2bfloat162_rn(p0, p1);
    float r0 = p0 - __bfloat162float(h.x);
    float r1 = p1 - __bfloat162float(h.y);
    __nv_bfloat162 l = __floats2bfloat162_rn(r0, r1);
    hi = *(uint32_t*)&h;
    lo = *(uint32_t*)&l;
}

// ---------------------------------------------------------------------------
// Tensor-core bf16 3-pass GEMM (unchanged core from R7).
// MODE 0: plain write, A from param. MODE 1: epilogue writes q/k/v as bf16
// hi/lo pairs (v transposed). MODE 2: A = G_INTER.
// ---------------------------------------------------------------------------
#define LDA 40

template<int MODE>
__global__ __launch_bounds__(256, 2)
void tc_gemm(const float* __restrict__ Ap, const float* __restrict__ Bm,
             const float* __restrict__ bias, float* __restrict__ C,
             int M, int N, int Kd)
{
    __shared__ __align__(16) uint16_t Ahi[128 * LDA];
    __shared__ __align__(16) uint16_t Alo[128 * LDA];
    __shared__ __align__(16) uint16_t Bhi[128 * LDA];
    __shared__ __align__(16) uint16_t Blo[128 * LDA];

    const float* A = (MODE == 2) ? G_INTER : Ap;
    const int tid  = threadIdx.x;
    const int wid  = tid >> 5;
    const int lane = tid & 31;
    const int m0 = blockIdx.y * 128;
    const int n0 = blockIdx.x * 128;
    const int wm = (wid & 3) * 32;
    const int wn = (wid >> 2) * 64;

    float c[2][8][4];
#pragma unroll
    for (int mf = 0; mf < 2; mf++)
#pragma unroll
        for (int nf = 0; nf < 8; nf++)
#pragma unroll
            for (int e = 0; e < 4; e++) c[mf][nf][e] = 0.f;

    const float* Abase = A  + (size_t)m0 * Kd;
    const float* Bbase = Bm + (size_t)n0 * Kd;

    const int nchunk = Kd >> 5;
    for (int ch = 0; ch < nchunk; ch++) {
        const int k0 = ch * 32;
        __syncthreads();

#pragma unroll
        for (int i = 0; i < 4; i++) {
            const int l = tid + i * 256;
            const int row = l >> 3;
            const int c4  = l & 7;
            {
                float4 v = *(const float4*)(Abase + (size_t)row * Kd + k0 + c4 * 4);
                __nv_bfloat162 h01 = __floats2bfloat162_rn(v.x, v.y);
                __nv_bfloat162 h23 = __floats2bfloat162_rn(v.z, v.w);
                float rx = v.x - __bfloat162float(h01.x);
                float ry = v.y - __bfloat162float(h01.y);
                float rz = v.z - __bfloat162float(h23.x);
                float rw = v.w - __bfloat162float(h23.y);
                __nv_bfloat162 l01 = __floats2bfloat162_rn(rx, ry);
                __nv_bfloat162 l23 = __floats2bfloat162_rn(rz, rw);
                *(uint2*)&Ahi[row * LDA + c4 * 4] = make_uint2(*(uint32_t*)&h01, *(uint32_t*)&h23);
                *(uint2*)&Alo[row * LDA + c4 * 4] = make_uint2(*(uint32_t*)&l01, *(uint32_t*)&l23);
            }
            {
                float4 v = *(const float4*)(Bbase + (size_t)row * Kd + k0 + c4 * 4);
                __nv_bfloat162 h01 = __floats2bfloat162_rn(v.x, v.y);
                __nv_bfloat162 h23 = __floats2bfloat162_rn(v.z, v.w);
                float rx = v.x - __bfloat162float(h01.x);
                float ry = v.y - __bfloat162float(h01.y);
                float rz = v.z - __bfloat162float(h23.x);
                float rw = v.w - __bfloat162float(h23.y);
                __nv_bfloat162 l01 = __floats2bfloat162_rn(rx, ry);
                __nv_bfloat162 l23 = __floats2bfloat162_rn(rz, rw);
                *(uint2*)&Bhi[row * LDA + c4 * 4] = make_uint2(*(uint32_t*)&h01, *(uint32_t*)&h23);
                *(uint2*)&Blo[row * LDA + c4 * 4] = make_uint2(*(uint32_t*)&l01, *(uint32_t*)&l23);
            }
        }
        __syncthreads();

#pragma unroll
        for (int ks = 0; ks < 2; ks++) {
            const int kc = ks * 16;
            const int arow = wm + (lane >> 2);
            const int acol = kc + (lane & 3) * 2;

            uint32_t ah[2][4], al[2][4];
#pragma unroll
            for (int mf = 0; mf < 2; mf++) {
                const int r = arow + mf * 16;
                ah[mf][0] = *(const uint32_t*)&Ahi[(r    ) * LDA + acol    ];
                ah[mf][1] = *(const uint32_t*)&Ahi[(r + 8) * LDA + acol    ];
                ah[mf][2] = *(const uint32_t*)&Ahi[(r    ) * LDA + acol + 8];
                ah[mf][3] = *(const uint32_t*)&Ahi[(r + 8) * LDA + acol + 8];
                al[mf][0] = *(const uint32_t*)&Alo[(r    ) * LDA + acol    ];
                al[mf][1] = *(const uint32_t*)&Alo[(r + 8) * LDA + acol    ];
                al[mf][2] = *(const uint32_t*)&Alo[(r    ) * LDA + acol + 8];
                al[mf][3] = *(const uint32_t*)&Alo[(r + 8) * LDA + acol + 8];
            }

#pragma unroll
            for (int nf = 0; nf < 8; nf++) {
                const int nrow = wn + nf * 8 + (lane >> 2);
                const int bcol = kc + (lane & 3) * 2;
                uint32_t bh0 = *(const uint32_t*)&Bhi[nrow * LDA + bcol    ];
                uint32_t bh1 = *(const uint32_t*)&Bhi[nrow * LDA + bcol + 8];
                uint32_t bl0 = *(const uint32_t*)&Blo[nrow * LDA + bcol    ];
                uint32_t bl1 = *(const uint32_t*)&Blo[nrow * LDA + bcol + 8];
#pragma unroll
                for (int mf = 0; mf < 2; mf++) {
                    mma_bf16(c[mf][nf], ah[mf][0], ah[mf][1], ah[mf][2], ah[mf][3], bh0, bh1);
                    mma_bf16(c[mf][nf], ah[mf][0], ah[mf][1], ah[mf][2], ah[mf][3], bl0, bl1);
                    mma_bf16(c[mf][nf], al[mf][0], al[mf][1], al[mf][2], al[mf][3], bh0, bh1);
                }
            }
        }
    }

    // ---- epilogue ----
#pragma unroll
    for (int mf = 0; mf < 2; mf++) {
#pragma unroll
        for (int nf = 0; nf < 8; nf++) {
            const int n = n0 + wn + nf * 8 + (lane & 3) * 2;
            const float2 bv = *(const float2*)(bias + n);
#pragma unroll
            for (int half = 0; half < 2; half++) {
                const int m = m0 + wm + mf * 16 + (lane >> 2) + half * 8;
                float2 r;
                r.x = c[mf][nf][half * 2 + 0] + bv.x;
                r.y = c[mf][nf][half * 2 + 1] + bv.y;
                if (MODE != 1) {
                    *(float2*)(C + (size_t)m * N + n) = r;
                } else {
                    const int which = n >> 10;
                    const int d = n & 1023;
                    const int h = d >> 6;
                    const int dh = d & 63;
                    const int b_ = m >> 11;
                    const int s_ = m & 2047;
                    const int bh_ = b_ * NHEADS + h;
                    __nv_bfloat162 hv = __floats2bfloat162_rn(r.x, r.y);
                    float rl0 = r.x - __bfloat162float(hv.x);
                    float rl1 = r.y - __bfloat162float(hv.y);
                    __nv_bfloat162 lv = __floats2bfloat162_rn(rl0, rl1);
                    if (which < 2) {
                        const size_t idx = ((size_t)bh_ * SEQ + s_) * DHEAD + dh;
                        __nv_bfloat16* hid = (which == 0) ? G_QHI : G_KHI;
                        __nv_bfloat16* lod = (which == 0) ? G_QLO : G_KLO;
                        *(uint32_t*)(hid + idx) = *(uint32_t*)&hv;
                        *(uint32_t*)(lod + idx) = *(uint32_t*)&lv;
                    } else {
                        // v transposed: [bh][dh][s]
                        const size_t idx = ((size_t)bh_ * DHEAD + dh) * SEQ + s_;
                        G_VHI[idx]       = hv.x;
                        G_VHI[idx + SEQ] = hv.y;
                        G_VLO[idx]       = lv.x;
                        G_VLO[idx + SEQ] = lv.y;
                    }
                }
            }
        }
    }
}

// ---------------------------------------------------------------------------
// Tensor-core causal flash attention (FA2-style, bf16 hi/lo 3-pass).
// 256 threads = 8 warps, each owns 16 q rows. Q tile 128, K tile 64.
// S C-fragments reused in-register as P A-fragments (layout identity).
// SMEM stride 72 bf16 -> conflict-free u32 fragment loads.
// ---------------------------------------------------------------------------
#define AST 72
#define ATTN_SMEM_BYTES ((2*128*AST + 4*64*AST) * 2)   // 73728 B

__global__ __launch_bounds__(256, 2)
void attn_mma()
{
    extern __shared__ __align__(16) uint16_t smb[];
    uint16_t* Qh = smb;                   // [128][72]
    uint16_t* Ql = Qh + 128 * AST;
    uint16_t* Kh = Ql + 128 * AST;        // [64][72]  (key, dh)
    uint16_t* Kl = Kh + 64 * AST;
    uint16_t* Vh = Kl + 64 * AST;         // [64][72]  (dh, key)
    uint16_t* Vl = Vh + 64 * AST;

    const int bh = blockIdx.x;
    const int qt = (int)(gridDim.y - 1 - blockIdx.y);   // big tiles first
    const int q0 = qt * 128;
    const int tid  = threadIdx.x;
    const int wq   = tid >> 5;
    const int lane = tid & 31;
    const int g  = lane >> 2;
    const int t4 = lane & 3;

    const uint16_t* qhi = (const uint16_t*)G_QHI;
    const uint16_t* qlo = (const uint16_t*)G_QLO;
    const uint16_t* khi = (const uint16_t*)G_KHI;
    const uint16_t* klo = (const uint16_t*)G_KLO;
    const uint16_t* vhi = (const uint16_t*)G_VHI;
    const uint16_t* vlo = (const uint16_t*)G_VLO;

    // ---- stage Q (hi+lo), 128 x 64 ----
    {
        const int r  = tid >> 1;
        const int c0 = (tid & 1) * 32;
        const size_t gi = ((size_t)bh * SEQ + q0 + r) * DHEAD + c0;
        const uint4* s1 = (const uint4*)(qhi + gi);
        const uint4* s2 = (const uint4*)(qlo + gi);
        uint4* d1 = (uint4*)(Qh + r * AST + c0);
        uint4* d2 = (uint4*)(Ql + r * AST + c0);
#pragma unroll
        for (int i = 0; i < 4; i++) { d1[i] = s1[i]; d2[i] = s2[i]; }
    }

    float o[8][4];
#pragma unroll
    for (int nf = 0; nf < 8; nf++)
#pragma unroll
        for (int e = 0; e < 4; e++) o[nf][e] = 0.f;
    float m2[2] = {-1e30f, -1e30f};
    float l2[2] = {0.f, 0.f};

    const int r0 = wq * 16;
    const int nkt = 2 * qt + 2;

    for (int kt = 0; kt < nkt; kt++) {
        const int k0 = kt * 64;
        __syncthreads();
        // ---- stage K (key,dh) and V (dh,key), hi+lo ----
        {
            const int r  = tid >> 2;           // 0..63
            const int c0 = (tid & 3) * 16;     // 0,16,32,48
            const size_t ki = ((size_t)bh * SEQ + k0 + r) * DHEAD + c0;
            *(uint4*)(Kh + r * AST + c0)     = *(const uint4*)(khi + ki);
            *(uint4*)(Kh + r * AST + c0 + 8) = *(const uint4*)(khi + ki + 8);
            *(uint4*)(Kl + r * AST + c0)     = *(const uint4*)(klo + ki);
            *(uint4*)(Kl + r * AST + c0 + 8) = *(const uint4*)(klo + ki + 8);
            const size_t vi = ((size_t)bh * DHEAD + r) * SEQ + k0 + c0;
            *(uint4*)(Vh + r * AST + c0)     = *(const uint4*)(vhi + vi);
            *(uint4*)(Vh + r * AST + c0 + 8) = *(const uint4*)(vhi + vi + 8);
            *(uint4*)(Vl + r * AST + c0)     = *(const uint4*)(vlo + vi);
            *(uint4*)(Vl + r * AST + c0 + 8) = *(const uint4*)(vlo + vi + 8);
        }
        __syncthreads();

        // ---- S = Q K^T (3 passes) ----
        float s[8][4];
#pragma unroll
        for (int nf = 0; nf < 8; nf++)
#pragma unroll
            for (int e = 0; e < 4; e++) s[nf][e] = 0.f;

#pragma unroll
        for (int kc = 0; kc < 64; kc += 16) {
            const int ac = kc + 2 * t4;
            uint32_t ah0 = *(const uint32_t*)&Qh[(r0 + g    ) * AST + ac    ];
            uint32_t ah1 = *(const uint32_t*)&Qh[(r0 + g + 8) * AST + ac    ];
            uint32_t ah2 = *(const uint32_t*)&Qh[(r0 + g    ) * AST + ac + 8];
            uint32_t ah3 = *(const uint32_t*)&Qh[(r0 + g + 8) * AST + ac + 8];
            uint32_t al0 = *(const uint32_t*)&Ql[(r0 + g    ) * AST + ac    ];
            uint32_t al1 = *(const uint32_t*)&Ql[(r0 + g + 8) * AST + ac    ];
            uint32_t al2 = *(const uint32_t*)&Ql[(r0 + g    ) * AST + ac + 8];
            uint32_t al3 = *(const uint32_t*)&Ql[(r0 + g + 8) * AST + ac + 8];
#pragma unroll
            for (int nf = 0; nf < 8; nf++) {
                const int kn = nf * 8 + g;
                uint32_t bh0 = *(const uint32_t*)&Kh[kn * AST + ac    ];
                uint32_t bh1 = *(const uint32_t*)&Kh[kn * AST + ac + 8];
                uint32_t bl0 = *(const uint32_t*)&Kl[kn * AST + ac    ];
                uint32_t bl1 = *(const uint32_t*)&Kl[kn * AST + ac + 8];
                mma_bf16(s[nf], ah0, ah1, ah2, ah3, bh0, bh1);
                mma_bf16(s[nf], ah0, ah1, ah2, ah3, bl0, bl1);
                mma_bf16(s[nf], al0, al1, al2, al3, bh0, bh1);
            }
        }

        // scale by 1/sqrt(Dh)
#pragma unroll
        for (int nf = 0; nf < 8; nf++)
#pragma unroll
            for (int e = 0; e < 4; e++) s[nf][e] *= 0.125f;

        // causal mask (only tiles touching the diagonal)
        if (kt >= 2 * qt) {
#pragma unroll
            for (int nf = 0; nf < 8; nf++)
#pragma unroll
                for (int e = 0; e < 4; e++) {
                    const int col = k0 + nf * 8 + t4 * 2 + (e & 1);
                    const int row = q0 + r0 + g + ((e >> 1) ? 8 : 0);
                    if (col > row) s[nf][e] = -1e30f;
                }
        }

        // ---- online softmax (rows r and r+8; stats across 4 lanes/group) ----
#pragma unroll
        for (int h = 0; h < 2; h++) {
            float mx = -1e30f;
#pragma unroll
            for (int nf = 0; nf < 8; nf++)
                mx = fmaxf(mx, fmaxf(s[nf][2 * h], s[nf][2 * h + 1]));
            mx = fmaxf(mx, __shfl_xor_sync(0xffffffffu, mx, 1));
            mx = fmaxf(mx, __shfl_xor_sync(0xffffffffu, mx, 2));
            const float mnew = fmaxf(m2[h], mx);
            const float corr = __expf(m2[h] - mnew);
            float ps = 0.f;
#pragma unroll
            for (int nf = 0; nf < 8; nf++) {
                float p0 = __expf(s[nf][2 * h    ] - mnew);
                float p1 = __expf(s[nf][2 * h + 1] - mnew);
                s[nf][2 * h] = p0; s[nf][2 * h + 1] = p1;
                ps += p0 + p1;
            }
            ps += __shfl_xor_sync(0xffffffffu, ps, 1);
            ps += __shfl_xor_sync(0xffffffffu, ps, 2);
            l2[h] = l2[h] * corr + ps;
            m2[h] = mnew;
#pragma unroll
            for (int nf = 0; nf < 8; nf++) {
                o[nf][2 * h] *= corr; o[nf][2 * h + 1] *= corr;
            }
        }

        // ---- O += P V (3 passes), P from registers ----
#pragma unroll
        for (int kg = 0; kg < 4; kg++) {
            uint32_t pa0, pa1, pa2, pa3, pl0, pl1, pl2, pl3;
            pack_hilo(s[2 * kg    ][0], s[2 * kg    ][1], pa0, pl0);
            pack_hilo(s[2 * kg    ][2], s[2 * kg    ][3], pa1, pl1);
            pack_hilo(s[2 * kg + 1][0], s[2 * kg + 1][1], pa2, pl2);
            pack_hilo(s[2 * kg + 1][2], s[2 * kg + 1][3], pa3, pl3);
            const int kc = kg * 16 + 2 * t4;
#pragma unroll
            for (int nf = 0; nf < 8; nf++) {
                const int dn = nf * 8 + g;
                uint32_t vh0 = *(const uint32_t*)&Vh[dn * AST + kc    ];
                uint32_t vh1 = *(const uint32_t*)&Vh[dn * AST + kc + 8];
                uint32_t vl0 = *(const uint32_t*)&Vl[dn * AST + kc    ];
                uint32_t vl1 = *(const uint32_t*)&Vl[dn * AST + kc + 8];
                mma_bf16(o[nf], pa0, pa1, pa2, pa3, vh0, vh1);
                mma_bf16(o[nf], pa0, pa1, pa2, pa3, vl0, vl1);
                mma_bf16(o[nf], pl0, pl1, pl2, pl3, vh0, vh1);
            }
        }
    }

    // ---- epilogue: normalize, write G_INTER fp32 [B,S,D] ----
    const int b_ = bh >> 4;
    const int head = bh & 15;
#pragma unroll
    for (int h = 0; h < 2; h++) {
        const float inv = 1.0f / l2[h];
        const int row = q0 + r0 + g + h * 8;
        float* dst = G_INTER + ((size_t)b_ * SEQ + row) * DMODEL + head * DHEAD;
#pragma unroll
        for (int nf = 0; nf < 8; nf++) {
            float2 r;
            r.x = o[nf][2 * h    ] * inv;
            r.y = o[nf][2 * h + 1] * inv;
            *(float2*)(dst + nf * 8 + 2 * t4) = r;
        }
    }
}

// ---------------------------------------------------------------------------
extern "C" void kernel_launch(void* const* d_in, const int* in_sizes, int n_in,
                              void* d_out, int out_size)
{
    const float* res    = (const float*)d_in[0];  // [2,2048,1024]
    const float* W_attn = (const float*)d_in[1];  // [3072,1024]
    const float* b_attn = (const float*)d_in[2];  // [3072]
    const float* W_O    = (const float*)d_in[3];  // [1024,1024]
    const float* b_O    = (const float*)d_in[4];  // [1024]
    float* out = (float*)d_out;                   // [2,2048,1024]

    cudaFuncSetAttribute(attn_mma, cudaFuncAttributeMaxDynamicSharedMemorySize,
                         ATTN_SMEM_BYTES);

    // 1. QKV projection (bf16 3-pass mma.sync) + fused bf16 hi/lo q/k/v write
    {
        dim3 grid(3 * DMODEL / 128, BATCH * SEQ / 128);   // (24, 32)
        tc_gemm<1><<<grid, 256>>>(res, W_attn, b_attn, nullptr,
                                  BATCH * SEQ, 3 * DMODEL, DMODEL);
    }
    // 2. Causal attention (tensor-core FA2, bf16 hi/lo 3-pass)
    {
        dim3 grid(BHD, SEQ / 128);                         // (32, 16)
        attn_mma<<<grid, 256, ATTN_SMEM_BYTES>>>();
    }
    // 3. Output projection (bf16 3-pass mma.sync, A = G_INTER)
    {
        dim3 grid(DMODEL / 128, BATCH * SEQ / 128);        // (8, 32)
        tc_gemm<2><<<grid, 256>>>(nullptr, W_O, b_O, out,
                                  BATCH * SEQ, DMODEL, DMODEL);
    }
}